// round 15
// baseline (speedup 1.0000x reference)
#include <cuda_runtime.h>
#include <cstdint>
#include <cstddef>

// LIF scan, chunked time + warm-up re-seeding (round 15).
// Light body from R14 (UB-free mask, pm-carry, FFMA warm-up, shuffle+LUT spike
// write-back, fused finalizer). NEW: C=16 chunks of 256 with TILE=32 so all
// 2048 warps fit in ONE wave (~13.8 warps/SM, 2x occupancy) — probing the
// 27us per-warp-latency floor that instruction cuts could not move.

constexpr int Bn    = 4096;
constexpr int Ln    = 4096;
constexpr int C     = 16;            // time chunks
constexpr int CHUNK = Ln / C;        // 256
constexpr int TILE  = 32;
constexpr int WT    = 10;            // warm-up tiles (H=320) for c >= 2
constexpr int MT    = CHUNK / TILE;  // 8 main tiles
constexpr int WPB   = 4;             // warps per block
constexpr int ROWSW = 32;            // rows per warp
constexpr int ROWSB = WPB * ROWSW;   // 128 rows per block
constexpr int RB    = Bn / ROWSB;    // 32 row-groups
constexpr int STRIDE = 36;           // 32 + 4 pad -> conflict-free LDS/STS.128
constexpr int WREG  = 2 * ROWSW * STRIDE;           // floats per warp region
constexpr int SMEM_BYTES = WPB * WREG * 4;          // 36864 B dynamic smem
constexpr int KTH   = 0x3F800000;    // bits(1.0f)

// nibble -> 4 spike floats; LUT[n][i] = (n>>i)&1
__constant__ float SPIKE_LUT[16][4] = {
    {0,0,0,0},{1,0,0,0},{0,1,0,0},{1,1,0,0},
    {0,0,1,0},{1,0,1,0},{0,1,1,0},{1,1,1,0},
    {0,0,0,1},{1,0,0,1},{0,1,0,1},{1,1,0,1},
    {0,0,1,1},{1,0,1,1},{0,1,1,1},{1,1,1,1}
};

__device__ int g_cnt [C * Bn];
__device__ int g_tsum[C * Bn];
__device__ int g_lat [C * Bn];
__device__ unsigned g_arrive[RB];    // zero-init; finalizer resets each launch

__device__ __forceinline__ unsigned smem_addr(const void* p) {
    return (unsigned)__cvta_generic_to_shared(p);
}

// UB-free "no-spike" mask: all-ones iff w < 1.0f, for ALL float bit patterns.
__device__ __forceinline__ int nospike_mask(int wi) {
    int d = (int)((unsigned)wi - (unsigned)KTH);   // wrapping, well-defined
    return (wi | d) >> 31;                         // sign(w<0) | sign(diff)
}

// Main step, exact rounding of ((w - w*0.05f) + I); spike -> w = I.
__device__ __forceinline__ float lif_step(float w, float Iv, int& pm) {
    float wns = __fadd_rn(__fsub_rn(w, __fmul_rn(w, 0.05f)), Iv);
    int wn = (__float_as_int(wns) & pm) | (__float_as_int(Iv) & ~pm);
    pm = nospike_mask(wn);
    return __int_as_float(wn);
}

// Warm step: FFMA form (1-ulp-class deviation, decays x0.95/step; warm only).
__device__ __forceinline__ float lif_step_warm(float w, float Iv, int& pm) {
    float wf = __fmaf_rn(w, 0.95f, Iv);
    int wn = (__float_as_int(wf) & pm) | (__float_as_int(Iv) & ~pm);
    pm = nospike_mask(wn);
    return __int_as_float(wn);
}

__device__ __forceinline__ int bitsum(unsigned mb) {
    return __popc(mb & 0xAAAAAAAAu)
         + 2  * __popc(mb & 0xCCCCCCCCu)
         + 4  * __popc(mb & 0xF0F0F0F0u)
         + 8  * __popc(mb & 0xFF00FF00u)
         + 16 * __popc(mb & 0xFFFF0000u);
}

__global__ void __launch_bounds__(WPB * 32)
lif_scan_kernel(const float* __restrict__ In, float* __restrict__ out) {
    extern __shared__ float smem[];
    __shared__ unsigned s_ticket;

    const int lane = threadIdx.x & 31;
    const int wid  = threadIdx.x >> 5;
    const int row0 = blockIdx.x * ROWSB + wid * ROWSW;   // this warp's 32 rows
    const int c    = blockIdx.y;

    // warm tiles: 0 for c==0; exact prefix (8 tiles = 256) for c==1; 10 else
    const int nwarm    = (c == 0) ? 0 : ((c == 1) ? MT : WT);
    const int nt       = nwarm + MT;                     // 8, 16 or 18 tiles
    const int col_base = c * CHUNK - nwarm * TILE;

    float* wbase = smem + wid * WREG;                    // warp-private region
    auto buf_row = [&](int t, int r) -> float* {
        return wbase + (t * ROWSW + r) * STRIDE;
    };

    // staging map (TILE=32): 8 passes of 16B/lane; pass k covers rows {4k..4k+3}
    const int crow = lane >> 3;             // 0..3
    const int ccol = (lane & 7) * 4;        // float index of this lane's float4
    // write-back transpose map: 8 iterations x (4 rows, 32 cols)
    const int crow2 = lane >> 3;            // 0..3
    const int ccol2 = (lane & 7) * 4;       // 0..28

    #pragma unroll
    for (int t = 0; t < 2; t++) {
        #pragma unroll
        for (int k = 0; k < 8; k++) {
            const int r = 4 * k + crow;
            const float* src = In + (size_t)(row0 + r) * Ln + col_base + t * TILE + ccol;
            unsigned dst = smem_addr(buf_row(t, r) + ccol);
            asm volatile("cp.async.cg.shared.global [%0], [%1], 16;" :: "r"(dst), "l"(src));
        }
        asm volatile("cp.async.commit_group;");
    }

    // w=0, pm=no-spike: first step -> (0-0)+I = I (v0 = 0), warm or main alike.
    float w  = 0.0f;
    int   pm = -1;

    int cnt  = 0;
    int tsum = 0;
    int lat  = Ln;

    for (int tile = 0; tile < nt; tile++) {
        if (tile < nt - 1) asm volatile("cp.async.wait_group 1;" ::: "memory");
        else               asm volatile("cp.async.wait_group 0;" ::: "memory");
        __syncwarp();

        float* buf = buf_row(tile & 1, lane);       // this lane's row
        const bool warm = (tile < nwarm);

        // batch-load this tile's 32 inputs into registers
        float v[32];
        #pragma unroll
        for (int g = 0; g < 8; g++)
            *reinterpret_cast<float4*>(v + 4 * g) =
                *reinterpret_cast<const float4*>(buf + 4 * g);

        // buffer fully consumed: overlap next prefetch with compute
        __syncwarp();
        if (tile + 2 < nt) {
            #pragma unroll
            for (int k = 0; k < 8; k++) {
                const int r = 4 * k + crow;
                const float* src = In + (size_t)(row0 + r) * Ln
                                 + col_base + (tile + 2) * TILE + ccol;
                unsigned dst = smem_addr(buf_row(tile & 1, r) + ccol);
                asm volatile("cp.async.cg.shared.global [%0], [%1], 16;"
                             :: "r"(dst), "l"(src));
            }
            asm volatile("cp.async.commit_group;");
        }

        if (warm) {
            #pragma unroll
            for (int e = 0; e < 32; e++) w = lif_step_warm(w, v[e], pm);
        } else {
            unsigned mb = 0;
            #pragma unroll
            for (int e = 0; e < 32; e++) {
                w = lif_step(w, v[e], pm);
                mb |= (1u << e) & (unsigned)~pm;          // spike bit
            }

            const int T = col_base + tile * TILE;

            // shuffle-transpose write-back with constant-LUT expansion
            #pragma unroll
            for (int k = 0; k < 8; k++) {
                const int r = 4 * k + crow2;
                unsigned mrow = __shfl_sync(0xffffffffu, mb, r);
                unsigned nib  = (mrow >> ccol2) & 0xFu;
                float4 f = *reinterpret_cast<const float4*>(SPIKE_LUT[nib]);
                *reinterpret_cast<float4*>(out + (size_t)(row0 + r) * Ln
                                           + T + ccol2) = f;
            }

            const int pc = __popc(mb);
            cnt  += pc;
            tsum += T * pc + bitsum(mb);
            if (lat == Ln && mb != 0u) lat = T + __ffs(mb) - 1;
        }
    }

    // store per-chunk partials; last-arriving chunk-block finalizes 128 rows
    const int idx = c * Bn + row0 + lane;
    g_cnt [idx] = cnt;
    g_tsum[idx] = tsum;
    g_lat [idx] = lat;
    __threadfence();
    __syncthreads();

    if (threadIdx.x == 0) s_ticket = atomicAdd(&g_arrive[blockIdx.x], 1u);
    __syncthreads();

    if (s_ticket == C - 1) {
        __threadfence();
        const int row = blockIdx.x * ROWSB + threadIdx.x;   // 128 rows, 128 threads
        int rcnt = 0, rts = 0, rlat = Ln;
        #pragma unroll
        for (int c2 = 0; c2 < C; c2++) {
            const int i = c2 * Bn + row;
            rcnt += g_cnt[i];
            rts  += g_tsum[i];
            rlat  = min(rlat, g_lat[i]);
        }
        out[(size_t)Bn * Ln + row]      = (float)rlat;
        out[(size_t)Bn * Ln + Bn + row] = (float)rts / ((float)rcnt + 1e-6f);
        if (threadIdx.x == 0) g_arrive[blockIdx.x] = 0;     // reset for replay
    }
}

extern "C" void kernel_launch(void* const* d_in, const int* in_sizes, int n_in,
                              void* d_out, int out_size) {
    (void)in_sizes; (void)n_in; (void)out_size;
    const float* In = (const float*)d_in[0];
    float* out = (float*)d_out;
    cudaFuncSetAttribute(lif_scan_kernel,
                         cudaFuncAttributeMaxDynamicSharedMemorySize, SMEM_BYTES);
    dim3 grid(RB, C);
    lif_scan_kernel<<<grid, WPB * 32, SMEM_BYTES>>>(In, out);
}

// round 16
// speedup vs baseline: 1.1957x; 1.1957x over previous
#include <cuda_runtime.h>
#include <cstdint>
#include <cstddef>

// LIF scan, chunked time + warm-up re-seeding (round 16).
// R14 base (C=8 chunks of 512, H=256 FFMA warm-up, 4-warp blocks, TILE=64,
// 2-buffer cp.async, UB-free spike mask, pm-carry, shuffle+LUT write-back,
// fused finalizer). NEW: register-level window double-buffering — the next
// 32-step window's batch-LDS (and the next tile's wait_group) are issued
// while the current window computes, removing the serial LDS/wait exposure
// at every window boundary.

constexpr int Bn    = 4096;
constexpr int Ln    = 4096;
constexpr int C     = 8;             // time chunks
constexpr int CHUNK = Ln / C;        // 512
constexpr int TILE  = 64;
constexpr int WT    = 4;             // warm-up tiles (H = 256)
constexpr int MT    = CHUNK / TILE;  // 8 main tiles
constexpr int WPB   = 4;             // warps per block
constexpr int ROWSW = 32;            // rows per warp
constexpr int ROWSB = WPB * ROWSW;   // 128 rows per block
constexpr int RB    = Bn / ROWSB;    // 32 row-groups
constexpr int STRIDE = 68;           // 64 + 4 pad -> conflict-free LDS/STS.128
constexpr int WREG  = 2 * ROWSW * STRIDE;           // floats per warp region
constexpr int SMEM_BYTES = WPB * WREG * 4;          // 69632 B dynamic smem
constexpr int KTH   = 0x3F800000;    // bits(1.0f)

// nibble -> 4 spike floats; LUT[n][i] = (n>>i)&1
__constant__ float SPIKE_LUT[16][4] = {
    {0,0,0,0},{1,0,0,0},{0,1,0,0},{1,1,0,0},
    {0,0,1,0},{1,0,1,0},{0,1,1,0},{1,1,1,0},
    {0,0,0,1},{1,0,0,1},{0,1,0,1},{1,1,0,1},
    {0,0,1,1},{1,0,1,1},{0,1,1,1},{1,1,1,1}
};

__device__ int g_cnt [C * Bn];
__device__ int g_tsum[C * Bn];
__device__ int g_lat [C * Bn];
__device__ unsigned g_arrive[RB];    // zero-init; finalizer resets each launch

__device__ __forceinline__ unsigned smem_addr(const void* p) {
    return (unsigned)__cvta_generic_to_shared(p);
}

// UB-free "no-spike" mask: all-ones iff w < 1.0f, for ALL float bit patterns.
__device__ __forceinline__ int nospike_mask(int wi) {
    int d = (int)((unsigned)wi - (unsigned)KTH);   // wrapping, well-defined
    return (wi | d) >> 31;                         // sign(w<0) | sign(diff)
}

// Main step, exact rounding of ((w - w*0.05f) + I); spike -> w = I.
__device__ __forceinline__ float lif_step(float w, float Iv, int& pm) {
    float wns = __fadd_rn(__fsub_rn(w, __fmul_rn(w, 0.05f)), Iv);
    int wn = (__float_as_int(wns) & pm) | (__float_as_int(Iv) & ~pm);
    pm = nospike_mask(wn);
    return __int_as_float(wn);
}

// Warm step: FFMA form (1-ulp-class deviation, decays x0.95/step; warm only).
__device__ __forceinline__ float lif_step_warm(float w, float Iv, int& pm) {
    float wf = __fmaf_rn(w, 0.95f, Iv);
    int wn = (__float_as_int(wf) & pm) | (__float_as_int(Iv) & ~pm);
    pm = nospike_mask(wn);
    return __int_as_float(wn);
}

__device__ __forceinline__ int bitsum(unsigned mb) {
    return __popc(mb & 0xAAAAAAAAu)
         + 2  * __popc(mb & 0xCCCCCCCCu)
         + 4  * __popc(mb & 0xF0F0F0F0u)
         + 8  * __popc(mb & 0xFF00FF00u)
         + 16 * __popc(mb & 0xFFFF0000u);
}

__global__ void __launch_bounds__(WPB * 32)
lif_scan_kernel(const float* __restrict__ In, float* __restrict__ out) {
    extern __shared__ float smem[];
    __shared__ unsigned s_ticket;

    const int lane = threadIdx.x & 31;
    const int wid  = threadIdx.x >> 5;
    const int row0 = blockIdx.x * ROWSB + wid * ROWSW;   // this warp's 32 rows
    const int c    = blockIdx.y;

    const int nwarm    = (c == 0) ? 0 : WT;
    const int nt       = nwarm + MT;                     // 8 or 12 tiles
    const int col_base = c * CHUNK - nwarm * TILE;

    float* wbase = smem + wid * WREG;                    // warp-private region
    auto buf_row = [&](int t, int r) -> float* {
        return wbase + (t * ROWSW + r) * STRIDE;
    };

    // staging map: 16 chunks of 16B; chunk k covers rows {2k, 2k+1}
    const int crow = lane >> 4;
    const int ccol = (lane & 15) * 4;
    // write-back transpose map: 8 iterations x (4 rows, 32 cols)
    const int crow2 = lane >> 3;            // 0..3
    const int ccol2 = (lane & 7) * 4;       // 0..28

    #pragma unroll
    for (int t = 0; t < 2; t++) {
        #pragma unroll
        for (int k = 0; k < 16; k++) {
            const int r = 2 * k + crow;
            const float* src = In + (size_t)(row0 + r) * Ln + col_base + t * TILE + ccol;
            unsigned dst = smem_addr(buf_row(t, r) + ccol);
            asm volatile("cp.async.cg.shared.global [%0], [%1], 16;" :: "r"(dst), "l"(src));
        }
        asm volatile("cp.async.commit_group;");
    }

    // w=0, pm=no-spike: first step -> (0-0)+I = I (v0 = 0).
    float w  = 0.0f;
    int   pm = -1;

    int cnt  = 0;
    int tsum = 0;
    int lat  = Ln;

    // window compute (32 steps) on register-resident inputs
    auto do_window = [&](const float* v, int T, bool record) {
        if (!record) {
            #pragma unroll
            for (int e = 0; e < 32; e++) w = lif_step_warm(w, v[e], pm);
        } else {
            unsigned mb = 0;
            #pragma unroll
            for (int e = 0; e < 32; e++) {
                w = lif_step(w, v[e], pm);
                mb |= (1u << e) & (unsigned)~pm;          // spike bit
            }
            // shuffle-transpose write-back with constant-LUT expansion
            #pragma unroll
            for (int k = 0; k < 8; k++) {
                const int r = 4 * k + crow2;
                unsigned mrow = __shfl_sync(0xffffffffu, mb, r);
                unsigned nib  = (mrow >> ccol2) & 0xFu;
                float4 f = *reinterpret_cast<const float4*>(SPIKE_LUT[nib]);
                *reinterpret_cast<float4*>(out + (size_t)(row0 + r) * Ln
                                           + T + ccol2) = f;
            }
            const int pc = __popc(mb);
            cnt  += pc;
            tsum += T * pc + bitsum(mb);
            if (lat == Ln && mb != 0u) lat = T + __ffs(mb) - 1;
        }
    };

    float vA[32], vB[32];

    // prologue: tile 0 ready, load window 0
    asm volatile("cp.async.wait_group 1;" ::: "memory");
    __syncwarp();
    {
        const float* buf = buf_row(0, lane);
        #pragma unroll
        for (int g = 0; g < 8; g++)
            *reinterpret_cast<float4*>(vA + 4 * g) =
                *reinterpret_cast<const float4*>(buf + 4 * g);
    }

    for (int tile = 0; tile < nt; tile++) {
        const int  bsel = tile & 1;
        const bool warm = (tile < nwarm);
        const float* buf = buf_row(bsel, lane);

        // load window 1 of this tile into vB (tile data already waited on)
        #pragma unroll
        for (int g = 0; g < 8; g++)
            *reinterpret_cast<float4*>(vB + 4 * g) =
                *reinterpret_cast<const float4*>(buf + 32 + 4 * g);

        // both windows of this buffer are register-resident across all lanes:
        // prefetch tile+2 into it, overlapping the two computes below.
        __syncwarp();
        if (tile + 2 < nt) {
            #pragma unroll
            for (int k = 0; k < 16; k++) {
                const int r = 2 * k + crow;
                const float* src = In + (size_t)(row0 + r) * Ln
                                 + col_base + (tile + 2) * TILE + ccol;
                unsigned dst = smem_addr(buf_row(bsel, r) + ccol);
                asm volatile("cp.async.cg.shared.global [%0], [%1], 16;"
                             :: "r"(dst), "l"(src));
            }
            asm volatile("cp.async.commit_group;");
        }

        // compute window 0
        do_window(vA, col_base + tile * TILE, !warm);

        // stage next tile's window 0 into vA while window 1 still pending
        if (tile + 1 < nt) {
            if (tile + 2 < nt) asm volatile("cp.async.wait_group 1;" ::: "memory");
            else               asm volatile("cp.async.wait_group 0;" ::: "memory");
            __syncwarp();
            const float* nbuf = buf_row((tile + 1) & 1, lane);
            #pragma unroll
            for (int g = 0; g < 8; g++)
                *reinterpret_cast<float4*>(vA + 4 * g) =
                    *reinterpret_cast<const float4*>(nbuf + 4 * g);
        }

        // compute window 1
        do_window(vB, col_base + tile * TILE + 32, !warm);
    }

    // store per-chunk partials; last-arriving chunk-block finalizes 128 rows
    const int idx = c * Bn + row0 + lane;
    g_cnt [idx] = cnt;
    g_tsum[idx] = tsum;
    g_lat [idx] = lat;
    __threadfence();
    __syncthreads();

    if (threadIdx.x == 0) s_ticket = atomicAdd(&g_arrive[blockIdx.x], 1u);
    __syncthreads();

    if (s_ticket == C - 1) {
        __threadfence();
        const int row = blockIdx.x * ROWSB + threadIdx.x;   // 128 rows, 128 threads
        int rcnt = 0, rts = 0, rlat = Ln;
        #pragma unroll
        for (int c2 = 0; c2 < C; c2++) {
            const int i = c2 * Bn + row;
            rcnt += g_cnt[i];
            rts  += g_tsum[i];
            rlat  = min(rlat, g_lat[i]);
        }
        out[(size_t)Bn * Ln + row]      = (float)rlat;
        out[(size_t)Bn * Ln + Bn + row] = (float)rts / ((float)rcnt + 1e-6f);
        if (threadIdx.x == 0) g_arrive[blockIdx.x] = 0;     // reset for replay
    }
}

extern "C" void kernel_launch(void* const* d_in, const int* in_sizes, int n_in,
                              void* d_out, int out_size) {
    (void)in_sizes; (void)n_in; (void)out_size;
    const float* In = (const float*)d_in[0];
    float* out = (float*)d_out;
    cudaFuncSetAttribute(lif_scan_kernel,
                         cudaFuncAttributeMaxDynamicSharedMemorySize, SMEM_BYTES);
    dim3 grid(RB, C);
    lif_scan_kernel<<<grid, WPB * 32, SMEM_BYTES>>>(In, out);
}

// round 17
// speedup vs baseline: 1.2685x; 1.0609x over previous
#include <cuda_runtime.h>
#include <cstdint>
#include <cstddef>

// LIF scan, chunked time + warm-up re-seeding (round 17, convergence).
// R14 structure (best scan: 26.9us): C=8 chunks of 512, H=256 FFMA warm-up,
// 4-warp blocks, TILE=64, 2-buffer cp.async, UB-free spike mask, pm-carry,
// shuffle+LUT spike write-back, fused finalizer.
// NEW: st.global.cs (evict-first) for the write-once spike plane to keep the
// 64MB output stream from thrashing L2 against input reads + warm L2 hits.

constexpr int Bn    = 4096;
constexpr int Ln    = 4096;
constexpr int C     = 8;             // time chunks
constexpr int CHUNK = Ln / C;        // 512
constexpr int TILE  = 64;
constexpr int WT    = 4;             // warm-up tiles (H = 256)
constexpr int MT    = CHUNK / TILE;  // 8 main tiles
constexpr int WPB   = 4;             // warps per block
constexpr int ROWSW = 32;            // rows per warp
constexpr int ROWSB = WPB * ROWSW;   // 128 rows per block
constexpr int RB    = Bn / ROWSB;    // 32 row-groups
constexpr int STRIDE = 68;           // 64 + 4 pad -> conflict-free LDS/STS.128
constexpr int WREG  = 2 * ROWSW * STRIDE;           // floats per warp region
constexpr int SMEM_BYTES = WPB * WREG * 4;          // 69632 B dynamic smem
constexpr int KTH   = 0x3F800000;    // bits(1.0f)

// nibble -> 4 spike floats; LUT[n][i] = (n>>i)&1
__constant__ float SPIKE_LUT[16][4] = {
    {0,0,0,0},{1,0,0,0},{0,1,0,0},{1,1,0,0},
    {0,0,1,0},{1,0,1,0},{0,1,1,0},{1,1,1,0},
    {0,0,0,1},{1,0,0,1},{0,1,0,1},{1,1,0,1},
    {0,0,1,1},{1,0,1,1},{0,1,1,1},{1,1,1,1}
};

__device__ int g_cnt [C * Bn];
__device__ int g_tsum[C * Bn];
__device__ int g_lat [C * Bn];
__device__ unsigned g_arrive[RB];    // zero-init; finalizer resets each launch

__device__ __forceinline__ unsigned smem_addr(const void* p) {
    return (unsigned)__cvta_generic_to_shared(p);
}

// UB-free "no-spike" mask: all-ones iff w < 1.0f, for ALL float bit patterns.
__device__ __forceinline__ int nospike_mask(int wi) {
    int d = (int)((unsigned)wi - (unsigned)KTH);   // wrapping, well-defined
    return (wi | d) >> 31;                         // sign(w<0) | sign(diff)
}

// Main step, exact rounding of ((w - w*0.05f) + I); spike -> w = I.
__device__ __forceinline__ float lif_step(float w, float Iv, int& pm) {
    float wns = __fadd_rn(__fsub_rn(w, __fmul_rn(w, 0.05f)), Iv);
    int wn = (__float_as_int(wns) & pm) | (__float_as_int(Iv) & ~pm);
    pm = nospike_mask(wn);
    return __int_as_float(wn);
}

// Warm step: FFMA form (1-ulp-class deviation, decays x0.95/step; warm only).
__device__ __forceinline__ float lif_step_warm(float w, float Iv, int& pm) {
    float wf = __fmaf_rn(w, 0.95f, Iv);
    int wn = (__float_as_int(wf) & pm) | (__float_as_int(Iv) & ~pm);
    pm = nospike_mask(wn);
    return __int_as_float(wn);
}

__device__ __forceinline__ int bitsum(unsigned mb) {
    return __popc(mb & 0xAAAAAAAAu)
         + 2  * __popc(mb & 0xCCCCCCCCu)
         + 4  * __popc(mb & 0xF0F0F0F0u)
         + 8  * __popc(mb & 0xFF00FF00u)
         + 16 * __popc(mb & 0xFFFF0000u);
}

// evict-first streaming 128-bit store (write-once output plane)
__device__ __forceinline__ void stg128_cs(float* p, float4 v) {
    asm volatile("st.global.cs.v4.f32 [%0], {%1, %2, %3, %4};"
                 :: "l"(p), "f"(v.x), "f"(v.y), "f"(v.z), "f"(v.w) : "memory");
}

__global__ void __launch_bounds__(WPB * 32)
lif_scan_kernel(const float* __restrict__ In, float* __restrict__ out) {
    extern __shared__ float smem[];
    __shared__ unsigned s_ticket;

    const int lane = threadIdx.x & 31;
    const int wid  = threadIdx.x >> 5;
    const int row0 = blockIdx.x * ROWSB + wid * ROWSW;   // this warp's 32 rows
    const int c    = blockIdx.y;

    const int nwarm    = (c == 0) ? 0 : WT;
    const int nt       = nwarm + MT;                     // 8 or 12 tiles
    const int col_base = c * CHUNK - nwarm * TILE;

    float* wbase = smem + wid * WREG;                    // warp-private region
    auto buf_row = [&](int t, int r) -> float* {
        return wbase + (t * ROWSW + r) * STRIDE;
    };

    // staging map: 16 chunks of 16B; chunk k covers rows {2k, 2k+1}
    const int crow = lane >> 4;
    const int ccol = (lane & 15) * 4;
    // write-back transpose map: 8 iterations x (4 rows, 32 cols)
    const int crow2 = lane >> 3;            // 0..3
    const int ccol2 = (lane & 7) * 4;       // 0..28

    #pragma unroll
    for (int t = 0; t < 2; t++) {
        #pragma unroll
        for (int k = 0; k < 16; k++) {
            const int r = 2 * k + crow;
            const float* src = In + (size_t)(row0 + r) * Ln + col_base + t * TILE + ccol;
            unsigned dst = smem_addr(buf_row(t, r) + ccol);
            asm volatile("cp.async.cg.shared.global [%0], [%1], 16;" :: "r"(dst), "l"(src));
        }
        asm volatile("cp.async.commit_group;");
    }

    // w=0, pm=no-spike: first step -> (0-0)+I = I (v0 = 0).
    float w  = 0.0f;
    int   pm = -1;

    int cnt  = 0;
    int tsum = 0;
    int lat  = Ln;

    for (int tile = 0; tile < nt; tile++) {
        if (tile < nt - 1) asm volatile("cp.async.wait_group 1;" ::: "memory");
        else               asm volatile("cp.async.wait_group 0;" ::: "memory");
        __syncwarp();

        float* buf = buf_row(tile & 1, lane);       // this lane's row
        const bool warm = (tile < nwarm);

        #pragma unroll
        for (int half = 0; half < 2; half++) {
            // batch-load this window's 32 inputs into registers
            float v[32];
            #pragma unroll
            for (int g = 0; g < 8; g++)
                *reinterpret_cast<float4*>(v + 4 * g) =
                    *reinterpret_cast<const float4*>(buf + half * 32 + 4 * g);

            // after window 1's batch-load the buffer is fully consumed:
            // overlap the next prefetch with window-1 compute.
            if (half == 1) {
                __syncwarp();
                if (tile + 2 < nt) {
                    #pragma unroll
                    for (int k = 0; k < 16; k++) {
                        const int r = 2 * k + crow;
                        const float* src = In + (size_t)(row0 + r) * Ln
                                         + col_base + (tile + 2) * TILE + ccol;
                        unsigned dst = smem_addr(buf_row(tile & 1, r) + ccol);
                        asm volatile("cp.async.cg.shared.global [%0], [%1], 16;"
                                     :: "r"(dst), "l"(src));
                    }
                    asm volatile("cp.async.commit_group;");
                }
            }

            if (warm) {
                #pragma unroll
                for (int e = 0; e < 32; e++) w = lif_step_warm(w, v[e], pm);
            } else {
                unsigned mb = 0;
                #pragma unroll
                for (int e = 0; e < 32; e++) {
                    w = lif_step(w, v[e], pm);
                    mb |= (1u << e) & (unsigned)~pm;          // spike bit
                }

                const int T = col_base + tile * TILE + half * 32;

                // shuffle-transpose write-back with constant-LUT expansion;
                // streaming (evict-first) stores for the write-once plane.
                #pragma unroll
                for (int k = 0; k < 8; k++) {
                    const int r = 4 * k + crow2;
                    unsigned mrow = __shfl_sync(0xffffffffu, mb, r);
                    unsigned nib  = (mrow >> ccol2) & 0xFu;
                    float4 f = *reinterpret_cast<const float4*>(SPIKE_LUT[nib]);
                    stg128_cs(out + (size_t)(row0 + r) * Ln + T + ccol2, f);
                }

                const int pc = __popc(mb);
                cnt  += pc;
                tsum += T * pc + bitsum(mb);
                if (lat == Ln && mb != 0u) lat = T + __ffs(mb) - 1;
            }
        }
    }

    // store per-chunk partials; last-arriving chunk-block finalizes 128 rows
    const int idx = c * Bn + row0 + lane;
    g_cnt [idx] = cnt;
    g_tsum[idx] = tsum;
    g_lat [idx] = lat;
    __threadfence();
    __syncthreads();

    if (threadIdx.x == 0) s_ticket = atomicAdd(&g_arrive[blockIdx.x], 1u);
    __syncthreads();

    if (s_ticket == C - 1) {
        __threadfence();
        const int row = blockIdx.x * ROWSB + threadIdx.x;   // 128 rows, 128 threads
        int rcnt = 0, rts = 0, rlat = Ln;
        #pragma unroll
        for (int c2 = 0; c2 < C; c2++) {
            const int i = c2 * Bn + row;
            rcnt += g_cnt[i];
            rts  += g_tsum[i];
            rlat  = min(rlat, g_lat[i]);
        }
        out[(size_t)Bn * Ln + row]      = (float)rlat;
        out[(size_t)Bn * Ln + Bn + row] = (float)rts / ((float)rcnt + 1e-6f);
        if (threadIdx.x == 0) g_arrive[blockIdx.x] = 0;     // reset for replay
    }
}

extern "C" void kernel_launch(void* const* d_in, const int* in_sizes, int n_in,
                              void* d_out, int out_size) {
    (void)in_sizes; (void)n_in; (void)out_size;
    const float* In = (const float*)d_in[0];
    float* out = (float*)d_out;
    cudaFuncSetAttribute(lif_scan_kernel,
                         cudaFuncAttributeMaxDynamicSharedMemorySize, SMEM_BYTES);
    dim3 grid(RB, C);
    lif_scan_kernel<<<grid, WPB * 32, SMEM_BYTES>>>(In, out);
}